// round 12
// baseline (speedup 1.0000x reference)
#include <cuda_runtime.h>
#include <cuda_bf16.h>
#include <cstdint>

// Problem constants
#define BDIM 1024
#define DIN  64
#define DHID 128
#define BN_EPS 1e-5f

typedef unsigned long long u64;

// Scratch (device globals; no allocations allowed)
__device__ float g_At[DHID * BDIM];   // A^T: [k][i]
__device__ float g_Ct[DHID * BDIM];   // C^T: [k][j]
__device__ float g_s[DHID];           // folded scale  gamma*rsigma*W2
__device__ float g_tpart[DHID];       // per-channel bias contribution
__device__ float g_t[1];              // folded bias
__device__ float g_P[BDIM];           // 0.5 * sum_k s_k * At[k][i]
__device__ float g_R[BDIM];           // 0.5 * sum_k s_k * Ct[k][j]

// ---------------------------------------------------------------------------
// Kernel 1: A^T / C^T precompute.  grid=256 blocks (4 rows each), 128 threads.
// (verbatim R1 — correct data orientation: x staged once per block)
// ---------------------------------------------------------------------------
__global__ __launch_bounds__(128) void prep_kernel(
    const float* __restrict__ x, const float* __restrict__ W1,
    const float* __restrict__ b1)
{
    __shared__ float xs[4][DIN];
    const int i0 = blockIdx.x * 4;
    const int tid = threadIdx.x;
    for (int e = tid; e < 4 * DIN; e += 128)
        xs[e >> 6][e & 63] = x[i0 * DIN + e];
    __syncthreads();

    const int k = tid;
    float accA[4], accC[4];
#pragma unroll
    for (int r = 0; r < 4; r++) { accA[r] = b1[k]; accC[r] = 0.f; }
#pragma unroll 8
    for (int d = 0; d < DIN; d++) {
        const float w1 = W1[d * DHID + k];
        const float w2 = W1[(d + DIN) * DHID + k];
#pragma unroll
        for (int r = 0; r < 4; r++) {
            const float xv = xs[r][d];
            accA[r] = fmaf(xv, w1, accA[r]);
            accC[r] = fmaf(xv, w2, accC[r]);
        }
    }
#pragma unroll
    for (int r = 0; r < 4; r++) {
        g_At[k * BDIM + i0 + r] = accA[r];
        g_Ct[k * BDIM + i0 + r] = accC[r];
    }
}

// ---------------------------------------------------------------------------
// Kernel 2: per-channel stats via 8 warp-local sorted chunks (verbatim R9).
// ---------------------------------------------------------------------------
__global__ __launch_bounds__(256) void sortstats_kernel(
    const float* __restrict__ gamma, const float* __restrict__ beta,
    const float* __restrict__ W2)
{
    __shared__ float sc[8 * 132];
    __shared__ float ssf[8 * 132];
    __shared__ float ssf2[8 * 132];
    __shared__ float wr1[8];
    __shared__ float wr2[8];

    const int k = blockIdx.x;
    const int tid = threadIdx.x;
    const int lane = tid & 31;
    const int warp = tid >> 5;

    const float4 cv = *(const float4*)&g_Ct[k * BDIM + tid * 4];
    float v[4] = {cv.x, cv.y, cv.z, cv.w};

    for (int size = 2; size <= 128; size <<= 1) {
        for (int stride = size >> 1; stride > 0; stride >>= 1) {
            float pv[4];
            if (stride >= 4) {
#pragma unroll
                for (int r = 0; r < 4; r++)
                    pv[r] = __shfl_xor_sync(0xffffffffu, v[r], stride >> 2);
            } else {
#pragma unroll
                for (int r = 0; r < 4; r++) pv[r] = v[r ^ stride];
            }
#pragma unroll
            for (int r = 0; r < 4; r++) {
                const int le = lane * 4 + r;
                const bool up = ((le & size) == 0);
                const bool lower = ((le & stride) == 0);
                const float mn = fminf(v[r], pv[r]);
                const float mx = fmaxf(v[r], pv[r]);
                v[r] = (up == lower) ? mn : mx;
            }
        }
    }

    float ls1[4], ls2[4];
    ls1[3] = v[3];               ls2[3] = v[3] * v[3];
    ls1[2] = ls1[3] + v[2];      ls2[2] = fmaf(v[2], v[2], ls2[3]);
    ls1[1] = ls1[2] + v[1];      ls2[1] = fmaf(v[1], v[1], ls2[2]);
    ls1[0] = ls1[1] + v[0];      ls2[0] = fmaf(v[0], v[0], ls2[1]);

    float w1 = ls1[0], w2 = ls2[0];
#pragma unroll
    for (int o = 1; o < 32; o <<= 1) {
        const float t1 = __shfl_down_sync(0xffffffffu, w1, o);
        const float t2 = __shfl_down_sync(0xffffffffu, w2, o);
        if (lane + o < 32) { w1 += t1; w2 += t2; }
    }
    const float base1 = w1 - ls1[0];
    const float base2 = w2 - ls2[0];

    const int cb = warp * 132;
#pragma unroll
    for (int r = 0; r < 4; r++) {
        const int le = lane * 4 + r;
        sc[cb + le]   = v[r];
        ssf[cb + le]  = ls1[r] + base1;
        ssf2[cb + le] = ls2[r] + base2;
    }
    if (lane == 0) {
        sc[cb + 128]   = __int_as_float(0x7f800000);
        ssf[cb + 128]  = 0.f;
        ssf2[cb + 128] = 0.f;
    }
    __syncthreads();

    const float4 av4 = *(const float4*)&g_At[k * BDIM + tid * 4];
    const float av[4] = {av4.x, av4.y, av4.z, av4.w};
    float S = 0.f, Q = 0.f;
#pragma unroll
    for (int r = 0; r < 4; r++) {
        const float a = av[r];
        const float th = -a;
        float ntot = 0.f, s1t = 0.f, s2t = 0.f;
#pragma unroll
        for (int m = 0; m < 8; m++) {
            const int base = m * 132;
            int lo = 0, hi = 128;
#pragma unroll
            for (int it = 0; it < 8; it++) {
                const int mid = (lo + hi) >> 1;
                if (sc[base + mid] > th) hi = mid; else lo = mid + 1;
            }
            ntot += (float)(128 - lo);
            s1t  += ssf[base + lo];
            s2t  += ssf2[base + lo];
        }
        S += fmaf(ntot, a, s1t);
        Q += fmaf(ntot * a, a, fmaf(2.f * a, s1t, s2t));
    }

#pragma unroll
    for (int o = 16; o > 0; o >>= 1) {
        S += __shfl_xor_sync(0xffffffffu, S, o);
        Q += __shfl_xor_sync(0xffffffffu, Q, o);
    }
    if (lane == 0) { wr1[warp] = S; wr2[warp] = Q; }
    __syncthreads();
    if (tid == 0) {
        float St = 0.f, Qt = 0.f;
#pragma unroll
        for (int w = 0; w < 8; w++) { St += wr1[w]; Qt += wr2[w]; }
        const float N = (float)BDIM * (float)BDIM;
        const float mean = St / N;
        const float var  = Qt / N - mean * mean;
        const float rs   = rsqrtf(var + BN_EPS);
        const float wk   = W2[k];
        g_s[k] = gamma[k] * rs * wk;
        g_tpart[k] = (beta[k] - mean * rs * gamma[k]) * wk;
    }
}

// ---------------------------------------------------------------------------
// Kernel 3: t / P / R  (verbatim R2)
// ---------------------------------------------------------------------------
__global__ __launch_bounds__(128) void finalize_pr_kernel(const float* __restrict__ b2)
{
    const int b = blockIdx.x;
    const int tid = threadIdx.x;
    if (b == 0) {
        __shared__ float red[128];
        red[tid] = g_tpart[tid];
        __syncthreads();
        for (int s = 64; s > 0; s >>= 1) {
            if (tid < s) red[tid] += red[tid + s];
            __syncthreads();
        }
        if (tid == 0) g_t[0] = red[0] + b2[0];
    } else {
        __shared__ float ss[DHID];
        ss[tid] = g_s[tid];
        __syncthreads();
        const bool isP = (b <= 8);
        const int idx = ((b - 1) & 7) * 128 + tid;
        const float* src = isP ? g_At : g_Ct;
        float acc = 0.f;
#pragma unroll 16
        for (int k = 0; k < DHID; k++)
            acc = fmaf(ss[k], src[k * BDIM + idx], acc);
        if (isP) g_P[idx] = 0.5f * acc;
        else     g_R[idx] = 0.5f * acc;
    }
}

// ---------------------------------------------------------------------------
// Kernel 4 (dominant): out[i][j] = t + P_i + R_j + sum_k (s_k/2)|At[k][i]+Ct[k][j]|
// 64x64 tile, 256 threads, 4i x 4j per thread; f32x2 packing along K:
// each u64 accumulator holds ONE output with (even-k, odd-k) partial sums.
// a-pairs and c-pairs load directly from k-interleaved smem -> no splat MOVs.
// ---------------------------------------------------------------------------
__global__ __launch_bounds__(256) void pass2_kernel(float* __restrict__ out)
{
    __shared__ u64 As2[32][64];    // [kp][i] = (At[2kp][i], At[2kp+1][i])  per chunk
    __shared__ u64 Cs2[32][64];    // [kp][j] = (Ct[2kp][j], Ct[2kp+1][j])
    __shared__ u64 s2p[64];        // (s[2m]/2, s[2m+1]/2) for all 64 k-pairs
    __shared__ float Ps[64];
    __shared__ float Rs[64];

    const int i0 = blockIdx.y * 64;
    const int j0 = blockIdx.x * 64;
    const int tid = threadIdx.x;

    if (tid < 64) {
        u64 p;
        asm("mov.b64 %0, {%1, %2};" : "=l"(p)
            : "f"(0.5f * g_s[2 * tid]), "f"(0.5f * g_s[2 * tid + 1]));
        s2p[tid] = p;
        Ps[tid] = g_P[i0 + tid];
    } else if (tid < 128) {
        Rs[tid - 64] = g_R[j0 + tid - 64];
    }

    const int ty = tid >> 4;   // 0..15 -> i sub-tile of 4
    const int tx = tid & 15;   // 0..15 -> j sub-tile of 4

    u64 acc2[4][4];   // [i][j], each = (even-k partial, odd-k partial)
#pragma unroll
    for (int q = 0; q < 4; q++)
#pragma unroll
        for (int r = 0; r < 4; r++) acc2[q][r] = 0ull;
    const u64 MASK = 0x7FFFFFFF7FFFFFFFull;

    for (int kc = 0; kc < 2; kc++) {
        __syncthreads();
        // interleave-load: 32 k-pairs x 16 i-quads, for A and C
        for (int e = tid; e < 32 * 16; e += 256) {
            const int kp = e >> 4, vv = e & 15;
            const int kg = kc * 64 + 2 * kp;
            const float4 alo = *(const float4*)&g_At[kg * BDIM + i0 + vv * 4];
            const float4 ahi = *(const float4*)&g_At[(kg + 1) * BDIM + i0 + vv * 4];
            const float4 clo = *(const float4*)&g_Ct[kg * BDIM + j0 + vv * 4];
            const float4 chi = *(const float4*)&g_Ct[(kg + 1) * BDIM + j0 + vv * 4];
            u64 p0, p1, p2, p3;
            asm("mov.b64 %0, {%1, %2};" : "=l"(p0) : "f"(alo.x), "f"(ahi.x));
            asm("mov.b64 %0, {%1, %2};" : "=l"(p1) : "f"(alo.y), "f"(ahi.y));
            asm("mov.b64 %0, {%1, %2};" : "=l"(p2) : "f"(alo.z), "f"(ahi.z));
            asm("mov.b64 %0, {%1, %2};" : "=l"(p3) : "f"(alo.w), "f"(ahi.w));
            *(ulonglong2*)&As2[kp][vv * 4]     = make_ulonglong2(p0, p1);
            *(ulonglong2*)&As2[kp][vv * 4 + 2] = make_ulonglong2(p2, p3);
            asm("mov.b64 %0, {%1, %2};" : "=l"(p0) : "f"(clo.x), "f"(chi.x));
            asm("mov.b64 %0, {%1, %2};" : "=l"(p1) : "f"(clo.y), "f"(chi.y));
            asm("mov.b64 %0, {%1, %2};" : "=l"(p2) : "f"(clo.z), "f"(chi.z));
            asm("mov.b64 %0, {%1, %2};" : "=l"(p3) : "f"(clo.w), "f"(chi.w));
            *(ulonglong2*)&Cs2[kp][vv * 4]     = make_ulonglong2(p0, p1);
            *(ulonglong2*)&Cs2[kp][vv * 4 + 2] = make_ulonglong2(p2, p3);
        }
        __syncthreads();

#pragma unroll 4
        for (int kp = 0; kp < 32; kp++) {
            const ulonglong2 a01 = *(const ulonglong2*)&As2[kp][ty * 4];
            const ulonglong2 a23 = *(const ulonglong2*)&As2[kp][ty * 4 + 2];
            const ulonglong2 c01 = *(const ulonglong2*)&Cs2[kp][tx * 4];
            const ulonglong2 c23 = *(const ulonglong2*)&Cs2[kp][tx * 4 + 2];
            const u64 sk = s2p[kc * 32 + kp];
            const u64 av[4] = {a01.x, a01.y, a23.x, a23.y};
            const u64 cv[4] = {c01.x, c01.y, c23.x, c23.y};
#pragma unroll
            for (int q = 0; q < 4; q++) {
#pragma unroll
                for (int r = 0; r < 4; r++) {
                    u64 vs;
                    asm("add.rn.f32x2 %0, %1, %2;" : "=l"(vs) : "l"(av[q]), "l"(cv[r]));
                    vs &= MASK;   // |.| on both packed k-lanes
                    asm("fma.rn.f32x2 %0, %1, %2, %3;"
                        : "=l"(acc2[q][r]) : "l"(vs), "l"(sk), "l"(acc2[q][r]));
                }
            }
        }
    }

    const float t = g_t[0];
    const float r0 = Rs[tx * 4 + 0];
    const float r1 = Rs[tx * 4 + 1];
    const float r2 = Rs[tx * 4 + 2];
    const float r3 = Rs[tx * 4 + 3];
#pragma unroll
    for (int q = 0; q < 4; q++) {
        float lo, hi;
        float4 o;
        asm("mov.b64 {%0, %1}, %2;" : "=f"(lo), "=f"(hi) : "l"(acc2[q][0]));
        o.x = lo + hi;
        asm("mov.b64 {%0, %1}, %2;" : "=f"(lo), "=f"(hi) : "l"(acc2[q][1]));
        o.y = lo + hi;
        asm("mov.b64 {%0, %1}, %2;" : "=f"(lo), "=f"(hi) : "l"(acc2[q][2]));
        o.z = lo + hi;
        asm("mov.b64 {%0, %1}, %2;" : "=f"(lo), "=f"(hi) : "l"(acc2[q][3]));
        o.w = lo + hi;
        const float base = t + Ps[ty * 4 + q];
        o.x += base + r0;
        o.y += base + r1;
        o.z += base + r2;
        o.w += base + r3;
        *(float4*)&out[(size_t)(i0 + ty * 4 + q) * BDIM + j0 + tx * 4] = o;
    }
}

// ---------------------------------------------------------------------------
extern "C" void kernel_launch(void* const* d_in, const int* in_sizes, int n_in,
                              void* d_out, int out_size)
{
    const float* x     = (const float*)d_in[0];
    const float* W1    = (const float*)d_in[1];
    const float* b1    = (const float*)d_in[2];
    const float* gamma = (const float*)d_in[3];
    const float* beta  = (const float*)d_in[4];
    const float* W2    = (const float*)d_in[5];
    const float* b2    = (const float*)d_in[6];
    float* out = (float*)d_out;

    prep_kernel<<<BDIM / 4, 128>>>(x, W1, b1);
    sortstats_kernel<<<DHID, 256>>>(gamma, beta, W2);
    finalize_pr_kernel<<<17, 128>>>(b2);
    pass2_kernel<<<dim3(16, 16), 256>>>(out);
}

// round 13
// speedup vs baseline: 1.2586x; 1.2586x over previous
#include <cuda_runtime.h>
#include <cuda_bf16.h>
#include <cstdint>

// Problem constants
#define BDIM 1024
#define DIN  64
#define DHID 128
#define BN_EPS 1e-5f

typedef unsigned long long u64;

// Scratch (device globals; no allocations allowed)
__device__ float g_At[DHID * BDIM];   // A^T: [k][i]
__device__ float g_Ct[DHID * BDIM];   // C^T: [k][j]
__device__ float g_s[DHID];           // folded scale  gamma*rsigma*W2
__device__ float g_t[1];              // folded bias (accumulated via atomics)
__device__ float g_P[BDIM];           // 0.5 * sum_k s_k * At[k][i]  (atomics)
__device__ float g_R[BDIM];           // 0.5 * sum_k s_k * Ct[k][j]  (atomics)

// ---------------------------------------------------------------------------
// Kernel 1: A^T / C^T precompute + zero the accumulators.
// grid=256 blocks (4 rows each), 128 threads.  (R1 verbatim + zeroing)
// ---------------------------------------------------------------------------
__global__ __launch_bounds__(128) void prep_kernel(
    const float* __restrict__ x, const float* __restrict__ W1,
    const float* __restrict__ b1)
{
    __shared__ float xs[4][DIN];
    const int i0 = blockIdx.x * 4;
    const int tid = threadIdx.x;

    // zero accumulators (256 blocks x 4 = 1024)
    if (tid < 4)      g_P[i0 + tid] = 0.f;
    else if (tid < 8) g_R[i0 + tid - 4] = 0.f;
    else if (tid == 8 && blockIdx.x == 0) g_t[0] = 0.f;

    for (int e = tid; e < 4 * DIN; e += 128)
        xs[e >> 6][e & 63] = x[i0 * DIN + e];
    __syncthreads();

    const int k = tid;
    float accA[4], accC[4];
#pragma unroll
    for (int r = 0; r < 4; r++) { accA[r] = b1[k]; accC[r] = 0.f; }
#pragma unroll 8
    for (int d = 0; d < DIN; d++) {
        const float w1 = W1[d * DHID + k];
        const float w2 = W1[(d + DIN) * DHID + k];
#pragma unroll
        for (int r = 0; r < 4; r++) {
            const float xv = xs[r][d];
            accA[r] = fmaf(xv, w1, accA[r]);
            accC[r] = fmaf(xv, w2, accC[r]);
        }
    }
#pragma unroll
    for (int r = 0; r < 4; r++) {
        g_At[k * BDIM + i0 + r] = accA[r];
        g_Ct[k * BDIM + i0 + r] = accC[r];
    }
}

// ---------------------------------------------------------------------------
// Kernel 2: per-channel stats via 8 warp-local sorted chunks (R9 verbatim),
// then BN fold + ATOMIC accumulation of P/R/t (replaces the finalize kernel).
// grid=128 blocks x 256 threads.
// ---------------------------------------------------------------------------
__global__ __launch_bounds__(256) void sortstats_kernel(
    const float* __restrict__ gamma, const float* __restrict__ beta,
    const float* __restrict__ W2)
{
    __shared__ float sc[8 * 132];
    __shared__ float ssf[8 * 132];
    __shared__ float ssf2[8 * 132];
    __shared__ float wr1[8];
    __shared__ float wr2[8];
    __shared__ float s_half;

    const int k = blockIdx.x;
    const int tid = threadIdx.x;
    const int lane = tid & 31;
    const int warp = tid >> 5;

    const float4 cv4 = *(const float4*)&g_Ct[k * BDIM + tid * 4];
    const float c[4] = {cv4.x, cv4.y, cv4.z, cv4.w};
    float v[4] = {c[0], c[1], c[2], c[3]};

    for (int size = 2; size <= 128; size <<= 1) {
        for (int stride = size >> 1; stride > 0; stride >>= 1) {
            float pv[4];
            if (stride >= 4) {
#pragma unroll
                for (int r = 0; r < 4; r++)
                    pv[r] = __shfl_xor_sync(0xffffffffu, v[r], stride >> 2);
            } else {
#pragma unroll
                for (int r = 0; r < 4; r++) pv[r] = v[r ^ stride];
            }
#pragma unroll
            for (int r = 0; r < 4; r++) {
                const int le = lane * 4 + r;
                const bool up = ((le & size) == 0);
                const bool lower = ((le & stride) == 0);
                const float mn = fminf(v[r], pv[r]);
                const float mx = fmaxf(v[r], pv[r]);
                v[r] = (up == lower) ? mn : mx;
            }
        }
    }

    float ls1[4], ls2[4];
    ls1[3] = v[3];               ls2[3] = v[3] * v[3];
    ls1[2] = ls1[3] + v[2];      ls2[2] = fmaf(v[2], v[2], ls2[3]);
    ls1[1] = ls1[2] + v[1];      ls2[1] = fmaf(v[1], v[1], ls2[2]);
    ls1[0] = ls1[1] + v[0];      ls2[0] = fmaf(v[0], v[0], ls2[1]);

    float w1 = ls1[0], w2 = ls2[0];
#pragma unroll
    for (int o = 1; o < 32; o <<= 1) {
        const float t1 = __shfl_down_sync(0xffffffffu, w1, o);
        const float t2 = __shfl_down_sync(0xffffffffu, w2, o);
        if (lane + o < 32) { w1 += t1; w2 += t2; }
    }
    const float base1 = w1 - ls1[0];
    const float base2 = w2 - ls2[0];

    const int cb = warp * 132;
#pragma unroll
    for (int r = 0; r < 4; r++) {
        const int le = lane * 4 + r;
        sc[cb + le]   = v[r];
        ssf[cb + le]  = ls1[r] + base1;
        ssf2[cb + le] = ls2[r] + base2;
    }
    if (lane == 0) {
        sc[cb + 128]   = __int_as_float(0x7f800000);
        ssf[cb + 128]  = 0.f;
        ssf2[cb + 128] = 0.f;
    }
    __syncthreads();

    const float4 av4 = *(const float4*)&g_At[k * BDIM + tid * 4];
    const float av[4] = {av4.x, av4.y, av4.z, av4.w};
    float S = 0.f, Q = 0.f;
#pragma unroll
    for (int r = 0; r < 4; r++) {
        const float a = av[r];
        const float th = -a;
        float ntot = 0.f, s1t = 0.f, s2t = 0.f;
#pragma unroll
        for (int m = 0; m < 8; m++) {
            const int base = m * 132;
            int lo = 0, hi = 128;
#pragma unroll
            for (int it = 0; it < 8; it++) {
                const int mid = (lo + hi) >> 1;
                if (sc[base + mid] > th) hi = mid; else lo = mid + 1;
            }
            ntot += (float)(128 - lo);
            s1t  += ssf[base + lo];
            s2t  += ssf2[base + lo];
        }
        S += fmaf(ntot, a, s1t);
        Q += fmaf(ntot * a, a, fmaf(2.f * a, s1t, s2t));
    }

#pragma unroll
    for (int o = 16; o > 0; o >>= 1) {
        S += __shfl_xor_sync(0xffffffffu, S, o);
        Q += __shfl_xor_sync(0xffffffffu, Q, o);
    }
    if (lane == 0) { wr1[warp] = S; wr2[warp] = Q; }
    __syncthreads();
    if (tid == 0) {
        float St = 0.f, Qt = 0.f;
#pragma unroll
        for (int w = 0; w < 8; w++) { St += wr1[w]; Qt += wr2[w]; }
        const float N = (float)BDIM * (float)BDIM;
        const float mean = St / N;
        const float var  = Qt / N - mean * mean;
        const float rs   = rsqrtf(var + BN_EPS);
        const float wk   = W2[k];
        const float sv   = gamma[k] * rs * wk;
        g_s[k] = sv;
        s_half = 0.5f * sv;
        atomicAdd(&g_t[0], (beta[k] - mean * rs * gamma[k]) * wk);
    }
    __syncthreads();

    // --- atomic P/R accumulation (replaces finalize kernel) ---
    const float sh = s_half;
#pragma unroll
    for (int r = 0; r < 4; r++) {
        atomicAdd(&g_P[tid * 4 + r], sh * av[r]);
        atomicAdd(&g_R[tid * 4 + r], sh * c[r]);
    }
}

// ---------------------------------------------------------------------------
// Kernel 3 (dominant): out[i][j] = t + P_i + R_j + sum_k (s_k/2)|At[k][i]+Ct[k][j]|
// (verbatim R2: 64x64 tile, 256 threads, 4i x 4j, j-packed f32x2)
// ---------------------------------------------------------------------------
__global__ __launch_bounds__(256) void pass2_kernel(
    const float* __restrict__ b2, float* __restrict__ out)
{
    __shared__ float As[64][64];   // [kk][i]
    __shared__ float Cs[64][64];   // [kk][j]
    __shared__ u64 s2h[DHID];      // (s/2, s/2) packed
    __shared__ float Ps[64];
    __shared__ float Rs[64];

    const int i0 = blockIdx.y * 64;
    const int j0 = blockIdx.x * 64;
    const int tid = threadIdx.x;

    if (tid < DHID) {
        u64 p;
        asm("mov.b64 %0, {%1, %1};" : "=l"(p) : "f"(0.5f * g_s[tid]));
        s2h[tid] = p;
    }
    if (tid < 64) Ps[tid] = g_P[i0 + tid];
    else if (tid < 128) Rs[tid - 64] = g_R[j0 + tid - 64];

    const int ty = tid >> 4;   // 0..15 -> i sub-tile of 4
    const int tx = tid & 15;   // 0..15 -> j sub-tile of 4

    u64 acc2[4][2];   // [i][jpair]
#pragma unroll
    for (int q = 0; q < 4; q++) { acc2[q][0] = 0ull; acc2[q][1] = 0ull; }
    const u64 MASK = 0x7FFFFFFF7FFFFFFFull;

    for (int kc = 0; kc < 2; kc++) {
        __syncthreads();
        for (int e = tid; e < 64 * 16; e += 256) {
            const int kk = e >> 4, vv = e & 15;
            const int kg = kc * 64 + kk;
            *(float4*)&As[kk][vv * 4] = *(const float4*)&g_At[kg * BDIM + i0 + vv * 4];
            *(float4*)&Cs[kk][vv * 4] = *(const float4*)&g_Ct[kg * BDIM + j0 + vv * 4];
        }
        __syncthreads();

#pragma unroll 8
        for (int kk = 0; kk < 64; kk++) {
            const float4 a4 = *(const float4*)&As[kk][ty * 4];
            const ulonglong2 cp = *(const ulonglong2*)&Cs[kk][tx * 4];
            const u64 sk = s2h[kc * 64 + kk];
            u64 av[4];
            asm("mov.b64 %0, {%1, %1};" : "=l"(av[0]) : "f"(a4.x));
            asm("mov.b64 %0, {%1, %1};" : "=l"(av[1]) : "f"(a4.y));
            asm("mov.b64 %0, {%1, %1};" : "=l"(av[2]) : "f"(a4.z));
            asm("mov.b64 %0, {%1, %1};" : "=l"(av[3]) : "f"(a4.w));
            const u64 cj[2] = {cp.x, cp.y};
#pragma unroll
            for (int q = 0; q < 4; q++) {
#pragma unroll
                for (int r = 0; r < 2; r++) {
                    u64 vs;
                    asm("add.rn.f32x2 %0, %1, %2;" : "=l"(vs) : "l"(av[q]), "l"(cj[r]));
                    vs &= MASK;   // |.| on both packed lanes
                    asm("fma.rn.f32x2 %0, %1, %2, %3;"
                        : "=l"(acc2[q][r]) : "l"(vs), "l"(sk), "l"(acc2[q][r]));
                }
            }
        }
    }

    const float t = g_t[0] + b2[0];
    const float r0 = Rs[tx * 4 + 0];
    const float r1 = Rs[tx * 4 + 1];
    const float r2 = Rs[tx * 4 + 2];
    const float r3 = Rs[tx * 4 + 3];
#pragma unroll
    for (int q = 0; q < 4; q++) {
        float v0, v1, v2, v3;
        asm("mov.b64 {%0, %1}, %2;" : "=f"(v0), "=f"(v1) : "l"(acc2[q][0]));
        asm("mov.b64 {%0, %1}, %2;" : "=f"(v2), "=f"(v3) : "l"(acc2[q][1]));
        const float base = t + Ps[ty * 4 + q];
        float4 o;
        o.x = v0 + base + r0;
        o.y = v1 + base + r1;
        o.z = v2 + base + r2;
        o.w = v3 + base + r3;
        *(float4*)&out[(size_t)(i0 + ty * 4 + q) * BDIM + j0 + tx * 4] = o;
    }
}

// ---------------------------------------------------------------------------
extern "C" void kernel_launch(void* const* d_in, const int* in_sizes, int n_in,
                              void* d_out, int out_size)
{
    const float* x     = (const float*)d_in[0];
    const float* W1    = (const float*)d_in[1];
    const float* b1    = (const float*)d_in[2];
    const float* gamma = (const float*)d_in[3];
    const float* beta  = (const float*)d_in[4];
    const float* W2    = (const float*)d_in[5];
    const float* b2    = (const float*)d_in[6];
    float* out = (float*)d_out;

    prep_kernel<<<BDIM / 4, 128>>>(x, W1, b1);
    sortstats_kernel<<<DHID, 256>>>(gamma, beta, W2);
    pass2_kernel<<<dim3(16, 16), 256>>>(b2, out);
}

// round 15
// speedup vs baseline: 1.2654x; 1.0054x over previous
#include <cuda_runtime.h>
#include <cuda_bf16.h>
#include <cstdint>

// Problem constants
#define BDIM 1024
#define DIN  64
#define DHID 128
#define BN_EPS 1e-5f
#define PREP_ROWS 8

typedef unsigned long long u64;

// Scratch (device globals; no allocations allowed)
__device__ float g_At[DHID * BDIM];   // A^T: [k][i]
__device__ float g_Ct[DHID * BDIM];   // C^T: [k][j]
__device__ float g_s[DHID];           // folded scale  gamma*rsigma*W2
__device__ float g_t[1];              // folded bias (accumulated via atomics)
__device__ float g_P[BDIM];           // 0.5 * sum_k s_k * At[k][i]  (atomics)
__device__ float g_R[BDIM];           // 0.5 * sum_k s_k * Ct[k][j]  (atomics)

// ---------------------------------------------------------------------------
// Kernel 1 (v2): A^T / C^T precompute + zero accumulators.
// grid=128 blocks (8 rows each), 256 threads = (k in 0..127, half in 0..1).
// W1 staged in dynamic smem via coalesced float4 copy (one latency exposure);
// compute loop is conflict-free LDS + FMA only.  h=0 -> A, h=1 -> C.
// ---------------------------------------------------------------------------
// dynamic smem: W1s [128*128 floats = 64KB] + xs [8*64 floats = 2KB]
#define PREP_SMEM_BYTES (2 * DIN * DHID * 4 + PREP_ROWS * DIN * 4)

__global__ __launch_bounds__(256) void prep_kernel(
    const float* __restrict__ x, const float* __restrict__ W1,
    const float* __restrict__ b1)
{
    extern __shared__ float psm[];
    float* W1s = psm;                       // [d][k] as in global: d*128 + k
    float* xs  = psm + 2 * DIN * DHID;      // [r][d]: r*64 + d

    const int i0 = blockIdx.x * PREP_ROWS;
    const int tid = threadIdx.x;
    const int k = tid & 127;
    const int h = tid >> 7;

    // zero accumulators (128 blocks x 8 = 1024)
    if (tid < PREP_ROWS)              g_P[i0 + tid] = 0.f;
    else if (tid < 2 * PREP_ROWS)     g_R[i0 + tid - PREP_ROWS] = 0.f;
    if (blockIdx.x == 0 && tid == 255) g_t[0] = 0.f;

    // cooperative coalesced copy: W1 (4096 float4) + x rows (128 float4)
    {
        const float4* Wv = (const float4*)W1;
        float4* Ws = (float4*)W1s;
#pragma unroll
        for (int e = 0; e < 16; e++)
            Ws[e * 256 + tid] = Wv[e * 256 + tid];
        const float4* xv = (const float4*)(x + (size_t)i0 * DIN);
        float4* xd = (float4*)xs;
        if (tid < PREP_ROWS * DIN / 4) xd[tid] = xv[tid];
    }
    __syncthreads();

    // h=0: acc over W1[0:64];  h=1: over W1[64:128]
    float acc[PREP_ROWS];
    const float init = (h == 0) ? b1[k] : 0.f;
#pragma unroll
    for (int r = 0; r < PREP_ROWS; r++) acc[r] = init;

    const float* wbase = W1s + h * DIN * DHID + k;
#pragma unroll
    for (int d4 = 0; d4 < DIN / 4; d4++) {
        float wv[4];
#pragma unroll
        for (int u = 0; u < 4; u++)
            wv[u] = wbase[(d4 * 4 + u) * DHID];
#pragma unroll
        for (int r = 0; r < PREP_ROWS; r++) {
            const float4 xv = *(const float4*)&xs[r * DIN + d4 * 4];
            acc[r] = fmaf(xv.x, wv[0], acc[r]);
            acc[r] = fmaf(xv.y, wv[1], acc[r]);
            acc[r] = fmaf(xv.z, wv[2], acc[r]);
            acc[r] = fmaf(xv.w, wv[3], acc[r]);
        }
    }

    float* dst = (h == 0) ? g_At : g_Ct;
    *(float4*)&dst[k * BDIM + i0]     = make_float4(acc[0], acc[1], acc[2], acc[3]);
    *(float4*)&dst[k * BDIM + i0 + 4] = make_float4(acc[4], acc[5], acc[6], acc[7]);
}

// ---------------------------------------------------------------------------
// Kernel 2: per-channel stats via 8 warp-local sorted chunks + BN fold +
// atomic P/R/t accumulation.  (verbatim R13, passed)
// ---------------------------------------------------------------------------
__global__ __launch_bounds__(256) void sortstats_kernel(
    const float* __restrict__ gamma, const float* __restrict__ beta,
    const float* __restrict__ W2)
{
    __shared__ float sc[8 * 132];
    __shared__ float ssf[8 * 132];
    __shared__ float ssf2[8 * 132];
    __shared__ float wr1[8];
    __shared__ float wr2[8];
    __shared__ float s_half;

    const int k = blockIdx.x;
    const int tid = threadIdx.x;
    const int lane = tid & 31;
    const int warp = tid >> 5;

    const float4 cv4 = *(const float4*)&g_Ct[k * BDIM + tid * 4];
    const float c[4] = {cv4.x, cv4.y, cv4.z, cv4.w};
    float v[4] = {c[0], c[1], c[2], c[3]};

    for (int size = 2; size <= 128; size <<= 1) {
        for (int stride = size >> 1; stride > 0; stride >>= 1) {
            float pv[4];
            if (stride >= 4) {
#pragma unroll
                for (int r = 0; r < 4; r++)
                    pv[r] = __shfl_xor_sync(0xffffffffu, v[r], stride >> 2);
            } else {
#pragma unroll
                for (int r = 0; r < 4; r++) pv[r] = v[r ^ stride];
            }
#pragma unroll
            for (int r = 0; r < 4; r++) {
                const int le = lane * 4 + r;
                const bool up = ((le & size) == 0);
                const bool lower = ((le & stride) == 0);
                const float mn = fminf(v[r], pv[r]);
                const float mx = fmaxf(v[r], pv[r]);
                v[r] = (up == lower) ? mn : mx;
            }
        }
    }

    float ls1[4], ls2[4];
    ls1[3] = v[3];               ls2[3] = v[3] * v[3];
    ls1[2] = ls1[3] + v[2];      ls2[2] = fmaf(v[2], v[2], ls2[3]);
    ls1[1] = ls1[2] + v[1];      ls2[1] = fmaf(v[1], v[1], ls2[2]);
    ls1[0] = ls1[1] + v[0];      ls2[0] = fmaf(v[0], v[0], ls2[1]);

    float w1 = ls1[0], w2 = ls2[0];
#pragma unroll
    for (int o = 1; o < 32; o <<= 1) {
        const float t1 = __shfl_down_sync(0xffffffffu, w1, o);
        const float t2 = __shfl_down_sync(0xffffffffu, w2, o);
        if (lane + o < 32) { w1 += t1; w2 += t2; }
    }
    const float base1 = w1 - ls1[0];
    const float base2 = w2 - ls2[0];

    const int cb = warp * 132;
#pragma unroll
    for (int r = 0; r < 4; r++) {
        const int le = lane * 4 + r;
        sc[cb + le]   = v[r];
        ssf[cb + le]  = ls1[r] + base1;
        ssf2[cb + le] = ls2[r] + base2;
    }
    if (lane == 0) {
        sc[cb + 128]   = __int_as_float(0x7f800000);
        ssf[cb + 128]  = 0.f;
        ssf2[cb + 128] = 0.f;
    }
    __syncthreads();

    const float4 av4 = *(const float4*)&g_At[k * BDIM + tid * 4];
    const float av[4] = {av4.x, av4.y, av4.z, av4.w};
    float S = 0.f, Q = 0.f;
#pragma unroll
    for (int r = 0; r < 4; r++) {
        const float a = av[r];
        const float th = -a;
        float ntot = 0.f, s1t = 0.f, s2t = 0.f;
#pragma unroll
        for (int m = 0; m < 8; m++) {
            const int base = m * 132;
            int lo = 0, hi = 128;
#pragma unroll
            for (int it = 0; it < 8; it++) {
                const int mid = (lo + hi) >> 1;
                if (sc[base + mid] > th) hi = mid; else lo = mid + 1;
            }
            ntot += (float)(128 - lo);
            s1t  += ssf[base + lo];
            s2t  += ssf2[base + lo];
        }
        S += fmaf(ntot, a, s1t);
        Q += fmaf(ntot * a, a, fmaf(2.f * a, s1t, s2t));
    }

#pragma unroll
    for (int o = 16; o > 0; o >>= 1) {
        S += __shfl_xor_sync(0xffffffffu, S, o);
        Q += __shfl_xor_sync(0xffffffffu, Q, o);
    }
    if (lane == 0) { wr1[warp] = S; wr2[warp] = Q; }
    __syncthreads();
    if (tid == 0) {
        float St = 0.f, Qt = 0.f;
#pragma unroll
        for (int w = 0; w < 8; w++) { St += wr1[w]; Qt += wr2[w]; }
        const float N = (float)BDIM * (float)BDIM;
        const float mean = St / N;
        const float var  = Qt / N - mean * mean;
        const float rs   = rsqrtf(var + BN_EPS);
        const float wk   = W2[k];
        const float sv   = gamma[k] * rs * wk;
        g_s[k] = sv;
        s_half = 0.5f * sv;
        atomicAdd(&g_t[0], (beta[k] - mean * rs * gamma[k]) * wk);
    }
    __syncthreads();

    const float sh = s_half;
#pragma unroll
    for (int r = 0; r < 4; r++) {
        atomicAdd(&g_P[tid * 4 + r], sh * av[r]);
        atomicAdd(&g_R[tid * 4 + r], sh * c[r]);
    }
}

// ---------------------------------------------------------------------------
// Kernel 3 (dominant): out[i][j] = t + P_i + R_j + sum_k (s_k/2)|At[k][i]+Ct[k][j]|
// (verbatim R2/R13: 64x64 tile, 256 threads, 4i x 4j, j-packed f32x2)
// ---------------------------------------------------------------------------
__global__ __launch_bounds__(256) void pass2_kernel(
    const float* __restrict__ b2, float* __restrict__ out)
{
    __shared__ float As[64][64];   // [kk][i]
    __shared__ float Cs[64][64];   // [kk][j]
    __shared__ u64 s2h[DHID];      // (s/2, s/2) packed
    __shared__ float Ps[64];
    __shared__ float Rs[64];

    const int i0 = blockIdx.y * 64;
    const int j0 = blockIdx.x * 64;
    const int tid = threadIdx.x;

    if (tid < DHID) {
        u64 p;
        asm("mov.b64 %0, {%1, %1};" : "=l"(p) : "f"(0.5f * g_s[tid]));
        s2h[tid] = p;
    }
    if (tid < 64) Ps[tid] = g_P[i0 + tid];
    else if (tid < 128) Rs[tid - 64] = g_R[j0 + tid - 64];

    const int ty = tid >> 4;   // 0..15 -> i sub-tile of 4
    const int tx = tid & 15;   // 0..15 -> j sub-tile of 4

    u64 acc2[4][2];   // [i][jpair]
#pragma unroll
    for (int q = 0; q < 4; q++) { acc2[q][0] = 0ull; acc2[q][1] = 0ull; }
    const u64 MASK = 0x7FFFFFFF7FFFFFFFull;

    for (int kc = 0; kc < 2; kc++) {
        __syncthreads();
        for (int e = tid; e < 64 * 16; e += 256) {
            const int kk = e >> 4, vv = e & 15;
            const int kg = kc * 64 + kk;
            *(float4*)&As[kk][vv * 4] = *(const float4*)&g_At[kg * BDIM + i0 + vv * 4];
            *(float4*)&Cs[kk][vv * 4] = *(const float4*)&g_Ct[kg * BDIM + j0 + vv * 4];
        }
        __syncthreads();

#pragma unroll 8
        for (int kk = 0; kk < 64; kk++) {
            const float4 a4 = *(const float4*)&As[kk][ty * 4];
            const ulonglong2 cp = *(const ulonglong2*)&Cs[kk][tx * 4];
            const u64 sk = s2h[kc * 64 + kk];
            u64 av[4];
            asm("mov.b64 %0, {%1, %1};" : "=l"(av[0]) : "f"(a4.x));
            asm("mov.b64 %0, {%1, %1};" : "=l"(av[1]) : "f"(a4.y));
            asm("mov.b64 %0, {%1, %1};" : "=l"(av[2]) : "f"(a4.z));
            asm("mov.b64 %0, {%1, %1};" : "=l"(av[3]) : "f"(a4.w));
            const u64 cj[2] = {cp.x, cp.y};
#pragma unroll
            for (int q = 0; q < 4; q++) {
#pragma unroll
                for (int r = 0; r < 2; r++) {
                    u64 vs;
                    asm("add.rn.f32x2 %0, %1, %2;" : "=l"(vs) : "l"(av[q]), "l"(cj[r]));
                    vs &= MASK;   // |.| on both packed lanes
                    asm("fma.rn.f32x2 %0, %1, %2, %3;"
                        : "=l"(acc2[q][r]) : "l"(vs), "l"(sk), "l"(acc2[q][r]));
                }
            }
        }
    }

    const float t = g_t[0] + b2[0];
    const float r0 = Rs[tx * 4 + 0];
    const float r1 = Rs[tx * 4 + 1];
    const float r2 = Rs[tx * 4 + 2];
    const float r3 = Rs[tx * 4 + 3];
#pragma unroll
    for (int q = 0; q < 4; q++) {
        float v0, v1, v2, v3;
        asm("mov.b64 {%0, %1}, %2;" : "=f"(v0), "=f"(v1) : "l"(acc2[q][0]));
        asm("mov.b64 {%0, %1}, %2;" : "=f"(v2), "=f"(v3) : "l"(acc2[q][1]));
        const float base = t + Ps[ty * 4 + q];
        float4 o;
        o.x = v0 + base + r0;
        o.y = v1 + base + r1;
        o.z = v2 + base + r2;
        o.w = v3 + base + r3;
        *(float4*)&out[(size_t)(i0 + ty * 4 + q) * BDIM + j0 + tx * 4] = o;
    }
}

// ---------------------------------------------------------------------------
extern "C" void kernel_launch(void* const* d_in, const int* in_sizes, int n_in,
                              void* d_out, int out_size)
{
    const float* x     = (const float*)d_in[0];
    const float* W1    = (const float*)d_in[1];
    const float* b1    = (const float*)d_in[2];
    const float* gamma = (const float*)d_in[3];
    const float* beta  = (const float*)d_in[4];
    const float* W2    = (const float*)d_in[5];
    const float* b2    = (const float*)d_in[6];
    float* out = (float*)d_out;

    cudaFuncSetAttribute(prep_kernel,
                         cudaFuncAttributeMaxDynamicSharedMemorySize, PREP_SMEM_BYTES);

    prep_kernel<<<BDIM / PREP_ROWS, 256, PREP_SMEM_BYTES>>>(x, W1, b1);
    sortstats_kernel<<<DHID, 256>>>(gamma, beta, W2);
    pass2_kernel<<<dim3(16, 16), 256>>>(b2, out);
}

// round 16
// speedup vs baseline: 1.3957x; 1.1030x over previous
#include <cuda_runtime.h>
#include <cuda_bf16.h>
#include <cstdint>

// Problem constants
#define BDIM 1024
#define DIN  64
#define DHID 128
#define BN_EPS 1e-5f
#define NBLK 256

typedef unsigned long long u64;

// Scratch (device globals; no allocations allowed)
__device__ float g_At[DHID * BDIM];   // A^T: [k][i]
__device__ float g_Ct[DHID * BDIM];   // C^T: [k][j]
__device__ float g_s[DHID];           // folded scale  gamma*rsigma*W2
__device__ float g_t[1];              // folded bias (atomics)
__device__ float g_P[BDIM];           // 0.5 * sum_k s_k * At[k][i]  (atomics)
__device__ float g_R[BDIM];           // 0.5 * sum_k s_k * Ct[k][j]  (atomics)
__device__ u64 g_cnt1;                // monotonic barrier counters (never reset)
__device__ u64 g_cnt2;

// dynamic smem: union of phase layouts
//  phase1: W1s 16384 floats + xs 256 floats
//  phase2: sc/ssf/ssf2 3*1056 floats
//  phase3: As 4096 + Cs 4096 + s2h 256 + Ps 64 + Rs 64
#define SMEM_FLOATS 16640
#define SMEM_BYTES (SMEM_FLOATS * 4)

// ---------------------------------------------------------------------------
// Grid-wide barrier: monotonic epoch counter, no resets needed across graph
// replays (each launch of 256 blocks advances the counter one 256-epoch).
// ---------------------------------------------------------------------------
__device__ __forceinline__ void grid_barrier(u64* cnt, u64* starget)
{
    __syncthreads();
    __threadfence();
    if (threadIdx.x == 0) {
        const u64 old = atomicAdd(cnt, 1ULL);
        *starget = old - (old & (u64)(NBLK - 1)) + (u64)NBLK;
    }
    __syncthreads();
    const u64 target = *starget;
    if (threadIdx.x == 0) {
        while (*(volatile u64*)cnt < target) __nanosleep(64);
    }
    __syncthreads();
    __threadfence();
}

// ---------------------------------------------------------------------------
// Fused kernel: prep -> barrier -> sortstats -> barrier -> pass2
// grid = 256 blocks x 256 threads (all co-resident: 2 blocks/SM).
// ---------------------------------------------------------------------------
__global__ __launch_bounds__(256) void fused_kernel(
    const float* __restrict__ x, const float* __restrict__ W1,
    const float* __restrict__ b1, const float* __restrict__ gamma,
    const float* __restrict__ beta, const float* __restrict__ W2,
    const float* __restrict__ b2, float* __restrict__ out)
{
    extern __shared__ float sm[];
    __shared__ u64 sbar;
    __shared__ float wr1[8];
    __shared__ float wr2[8];
    __shared__ float s_half;

    const int bid = blockIdx.x;
    const int tid = threadIdx.x;
    const int lane = tid & 31;
    const int warp = tid >> 5;

    // ======================= Phase 1: prep (R15, 4 rows/block) ==============
    {
        float* W1s = sm;                 // [d*128 + k]
        float* xs  = sm + 2 * DIN * DHID;// [r*64 + d]
        const int i0 = bid * 4;
        const int k = tid & 127;
        const int h = tid >> 7;

        // zero accumulators (256 blocks x 4 = 1024)
        if (tid < 4)      g_P[i0 + tid] = 0.f;
        else if (tid < 8) g_R[i0 + tid - 4] = 0.f;
        if (bid == 0 && tid == 255) g_t[0] = 0.f;

        // coalesced copy: W1 (4096 float4), x rows (64 float4)
        {
            const float4* Wv = (const float4*)W1;
            float4* Ws = (float4*)W1s;
#pragma unroll
            for (int e = 0; e < 16; e++)
                Ws[e * 256 + tid] = Wv[e * 256 + tid];
            const float4* xv = (const float4*)(x + (size_t)i0 * DIN);
            float4* xd = (float4*)xs;
            if (tid < 64) xd[tid] = xv[tid];
        }
        __syncthreads();

        float acc[4];
        const float init = (h == 0) ? b1[k] : 0.f;
#pragma unroll
        for (int r = 0; r < 4; r++) acc[r] = init;

        const float* wbase = W1s + h * DIN * DHID + k;
#pragma unroll
        for (int d4 = 0; d4 < DIN / 4; d4++) {
            float wv[4];
#pragma unroll
            for (int u = 0; u < 4; u++)
                wv[u] = wbase[(d4 * 4 + u) * DHID];
#pragma unroll
            for (int r = 0; r < 4; r++) {
                const float4 xv = *(const float4*)&xs[r * DIN + d4 * 4];
                acc[r] = fmaf(xv.x, wv[0], acc[r]);
                acc[r] = fmaf(xv.y, wv[1], acc[r]);
                acc[r] = fmaf(xv.z, wv[2], acc[r]);
                acc[r] = fmaf(xv.w, wv[3], acc[r]);
            }
        }
        float* dst = (h == 0) ? g_At : g_Ct;
        *(float4*)&dst[k * BDIM + i0] = make_float4(acc[0], acc[1], acc[2], acc[3]);
    }

    grid_barrier(&g_cnt1, &sbar);

    // ======================= Phase 2: sortstats (R13) on blocks 0..127 ======
    if (bid < DHID) {
        float* sc   = sm;                // 8*132
        float* ssf  = sm + 1056;
        float* ssf2 = sm + 2112;
        const int k = bid;

        const float4 cv4 = *(const float4*)&g_Ct[k * BDIM + tid * 4];
        const float c[4] = {cv4.x, cv4.y, cv4.z, cv4.w};
        float v[4] = {c[0], c[1], c[2], c[3]};

        for (int size = 2; size <= 128; size <<= 1) {
            for (int stride = size >> 1; stride > 0; stride >>= 1) {
                float pv[4];
                if (stride >= 4) {
#pragma unroll
                    for (int r = 0; r < 4; r++)
                        pv[r] = __shfl_xor_sync(0xffffffffu, v[r], stride >> 2);
                } else {
#pragma unroll
                    for (int r = 0; r < 4; r++) pv[r] = v[r ^ stride];
                }
#pragma unroll
                for (int r = 0; r < 4; r++) {
                    const int le = lane * 4 + r;
                    const bool up = ((le & size) == 0);
                    const bool lower = ((le & stride) == 0);
                    const float mn = fminf(v[r], pv[r]);
                    const float mx = fmaxf(v[r], pv[r]);
                    v[r] = (up == lower) ? mn : mx;
                }
            }
        }

        float ls1[4], ls2[4];
        ls1[3] = v[3];               ls2[3] = v[3] * v[3];
        ls1[2] = ls1[3] + v[2];      ls2[2] = fmaf(v[2], v[2], ls2[3]);
        ls1[1] = ls1[2] + v[1];      ls2[1] = fmaf(v[1], v[1], ls2[2]);
        ls1[0] = ls1[1] + v[0];      ls2[0] = fmaf(v[0], v[0], ls2[1]);

        float w1 = ls1[0], w2 = ls2[0];
#pragma unroll
        for (int o = 1; o < 32; o <<= 1) {
            const float t1 = __shfl_down_sync(0xffffffffu, w1, o);
            const float t2 = __shfl_down_sync(0xffffffffu, w2, o);
            if (lane + o < 32) { w1 += t1; w2 += t2; }
        }
        const float base1 = w1 - ls1[0];
        const float base2 = w2 - ls2[0];

        const int cb = warp * 132;
#pragma unroll
        for (int r = 0; r < 4; r++) {
            const int le = lane * 4 + r;
            sc[cb + le]   = v[r];
            ssf[cb + le]  = ls1[r] + base1;
            ssf2[cb + le] = ls2[r] + base2;
        }
        if (lane == 0) {
            sc[cb + 128]   = __int_as_float(0x7f800000);
            ssf[cb + 128]  = 0.f;
            ssf2[cb + 128] = 0.f;
        }
        __syncthreads();

        const float4 av4 = *(const float4*)&g_At[k * BDIM + tid * 4];
        const float av[4] = {av4.x, av4.y, av4.z, av4.w};
        float S = 0.f, Q = 0.f;
#pragma unroll
        for (int r = 0; r < 4; r++) {
            const float a = av[r];
            const float th = -a;
            float ntot = 0.f, s1t = 0.f, s2t = 0.f;
#pragma unroll
            for (int m = 0; m < 8; m++) {
                const int base = m * 132;
                int lo = 0, hi = 128;
#pragma unroll
                for (int it = 0; it < 8; it++) {
                    const int mid = (lo + hi) >> 1;
                    if (sc[base + mid] > th) hi = mid; else lo = mid + 1;
                }
                ntot += (float)(128 - lo);
                s1t  += ssf[base + lo];
                s2t  += ssf2[base + lo];
            }
            S += fmaf(ntot, a, s1t);
            Q += fmaf(ntot * a, a, fmaf(2.f * a, s1t, s2t));
        }

#pragma unroll
        for (int o = 16; o > 0; o >>= 1) {
            S += __shfl_xor_sync(0xffffffffu, S, o);
            Q += __shfl_xor_sync(0xffffffffu, Q, o);
        }
        if (lane == 0) { wr1[warp] = S; wr2[warp] = Q; }
        __syncthreads();
        if (tid == 0) {
            float St = 0.f, Qt = 0.f;
#pragma unroll
            for (int w = 0; w < 8; w++) { St += wr1[w]; Qt += wr2[w]; }
            const float N = (float)BDIM * (float)BDIM;
            const float mean = St / N;
            const float var  = Qt / N - mean * mean;
            const float rs   = rsqrtf(var + BN_EPS);
            const float wk   = W2[k];
            const float sv   = gamma[k] * rs * wk;
            g_s[k] = sv;
            s_half = 0.5f * sv;
            atomicAdd(&g_t[0], (beta[k] - mean * rs * gamma[k]) * wk);
        }
        __syncthreads();

        const float sh = s_half;
#pragma unroll
        for (int r = 0; r < 4; r++) {
            atomicAdd(&g_P[tid * 4 + r], sh * av[r]);
            atomicAdd(&g_R[tid * 4 + r], sh * c[r]);
        }
    }

    grid_barrier(&g_cnt2, &sbar);

    // ======================= Phase 3: pass2 (R2) =============================
    {
        float* As  = sm;                       // [kk][i]: kk*64 + i
        float* Cs  = sm + 4096;                // [kk][j]
        u64*   s2h = (u64*)(sm + 8192);        // 128 u64
        float* Ps  = sm + 8448;
        float* Rs  = sm + 8512;

        const int i0 = (bid >> 4) * 64;
        const int j0 = (bid & 15) * 64;

        if (tid < DHID) {
            u64 p;
            asm("mov.b64 %0, {%1, %1};" : "=l"(p) : "f"(0.5f * g_s[tid]));
            s2h[tid] = p;
        }
        if (tid < 64) Ps[tid] = g_P[i0 + tid];
        else if (tid < 128) Rs[tid - 64] = g_R[j0 + tid - 64];

        const int ty = tid >> 4;
        const int tx = tid & 15;

        u64 acc2[4][2];
#pragma unroll
        for (int q = 0; q < 4; q++) { acc2[q][0] = 0ull; acc2[q][1] = 0ull; }
        const u64 MASK = 0x7FFFFFFF7FFFFFFFull;

        for (int kc = 0; kc < 2; kc++) {
            __syncthreads();
            for (int e = tid; e < 64 * 16; e += 256) {
                const int kk = e >> 4, vv = e & 15;
                const int kg = kc * 64 + kk;
                *(float4*)&As[kk * 64 + vv * 4] = *(const float4*)&g_At[kg * BDIM + i0 + vv * 4];
                *(float4*)&Cs[kk * 64 + vv * 4] = *(const float4*)&g_Ct[kg * BDIM + j0 + vv * 4];
            }
            __syncthreads();

#pragma unroll 8
            for (int kk = 0; kk < 64; kk++) {
                const float4 a4 = *(const float4*)&As[kk * 64 + ty * 4];
                const ulonglong2 cp = *(const ulonglong2*)&Cs[kk * 64 + tx * 4];
                const u64 sk = s2h[kc * 64 + kk];
                u64 av[4];
                asm("mov.b64 %0, {%1, %1};" : "=l"(av[0]) : "f"(a4.x));
                asm("mov.b64 %0, {%1, %1};" : "=l"(av[1]) : "f"(a4.y));
                asm("mov.b64 %0, {%1, %1};" : "=l"(av[2]) : "f"(a4.z));
                asm("mov.b64 %0, {%1, %1};" : "=l"(av[3]) : "f"(a4.w));
                const u64 cj[2] = {cp.x, cp.y};
#pragma unroll
                for (int q = 0; q < 4; q++) {
#pragma unroll
                    for (int r = 0; r < 2; r++) {
                        u64 vs;
                        asm("add.rn.f32x2 %0, %1, %2;" : "=l"(vs) : "l"(av[q]), "l"(cj[r]));
                        vs &= MASK;
                        asm("fma.rn.f32x2 %0, %1, %2, %3;"
                            : "=l"(acc2[q][r]) : "l"(vs), "l"(sk), "l"(acc2[q][r]));
                    }
                }
            }
        }

        const float t = g_t[0] + b2[0];
        const float r0 = Rs[tx * 4 + 0];
        const float r1 = Rs[tx * 4 + 1];
        const float r2 = Rs[tx * 4 + 2];
        const float r3 = Rs[tx * 4 + 3];
#pragma unroll
        for (int q = 0; q < 4; q++) {
            float v0, v1, v2, v3;
            asm("mov.b64 {%0, %1}, %2;" : "=f"(v0), "=f"(v1) : "l"(acc2[q][0]));
            asm("mov.b64 {%0, %1}, %2;" : "=f"(v2), "=f"(v3) : "l"(acc2[q][1]));
            const float base = t + Ps[ty * 4 + q];
            float4 o;
            o.x = v0 + base + r0;
            o.y = v1 + base + r1;
            o.z = v2 + base + r2;
            o.w = v3 + base + r3;
            *(float4*)&out[(size_t)(i0 + ty * 4 + q) * BDIM + j0 + tx * 4] = o;
        }
    }
}

// ---------------------------------------------------------------------------
extern "C" void kernel_launch(void* const* d_in, const int* in_sizes, int n_in,
                              void* d_out, int out_size)
{
    const float* x     = (const float*)d_in[0];
    const float* W1    = (const float*)d_in[1];
    const float* b1    = (const float*)d_in[2];
    const float* gamma = (const float*)d_in[3];
    const float* beta  = (const float*)d_in[4];
    const float* W2    = (const float*)d_in[5];
    const float* b2    = (const float*)d_in[6];
    float* out = (float*)d_out;

    cudaFuncSetAttribute(fused_kernel,
                         cudaFuncAttributeMaxDynamicSharedMemorySize, SMEM_BYTES);

    fused_kernel<<<NBLK, 256, SMEM_BYTES>>>(x, W1, b1, gamma, beta, W2, b2, out);
}

// round 17
// speedup vs baseline: 1.4748x; 1.0567x over previous
#include <cuda_runtime.h>
#include <cuda_bf16.h>
#include <cstdint>

// Problem constants
#define BDIM 1024
#define DIN  64
#define DHID 128
#define BN_EPS 1e-5f
#define NBLK 256

typedef unsigned long long u64;

// Scratch (device globals; no allocations allowed)
__device__ float g_At[DHID * BDIM];   // A^T: [k][i]
__device__ float g_Ct[DHID * BDIM];   // C^T: [k][j]
__device__ float g_s[DHID];           // folded scale  gamma*rsigma*W2
__device__ float g_t[1];              // folded bias (atomics)
__device__ float g_P[BDIM];           // 0.5 * sum_k s_k * At[k][i]  (atomics)
__device__ float g_R[BDIM];           // 0.5 * sum_k s_k * Ct[k][j]  (atomics)
__device__ u64 g_cnt1;                // monotonic barrier counters (never reset)
__device__ u64 g_cnt2;

// dynamic smem union (floats):
//  phase1: W1 half 8192 + xs 512                      = 8704
//  phase2: sc/ssf/ssf2 3*1056                         = 3168
//  phase3: As 4096 + Cs 4096 + s2h 256 + Ps/Rs 128    = 8576
#define SMEM_FLOATS 8704
#define SMEM_BYTES (SMEM_FLOATS * 4)

// ---------------------------------------------------------------------------
// Grid-wide barrier: monotonic epoch counter, no resets needed across graph
// replays (each launch of 256 blocks advances the counter one 256-epoch).
// ---------------------------------------------------------------------------
__device__ __forceinline__ void grid_barrier(u64* cnt, u64* starget)
{
    __syncthreads();
    __threadfence();
    if (threadIdx.x == 0) {
        const u64 old = atomicAdd(cnt, 1ULL);
        *starget = old - (old & (u64)(NBLK - 1)) + (u64)NBLK;
    }
    __syncthreads();
    const u64 target = *starget;
    if (threadIdx.x == 0) {
        while (*(volatile u64*)cnt < target) __nanosleep(64);
    }
    __syncthreads();
    __threadfence();
}

// ---------------------------------------------------------------------------
// Fused kernel: prep(A/C split) -> barrier -> sortstats -> barrier -> pass2
// grid = 256 blocks x 256 threads (all co-resident: 2 blocks/SM).
// ---------------------------------------------------------------------------
__global__ __launch_bounds__(256) void fused_kernel(
    const float* __restrict__ x, const float* __restrict__ W1,
    const float* __restrict__ b1, const float* __restrict__ gamma,
    const float* __restrict__ beta, const float* __restrict__ W2,
    const float* __restrict__ b2, float* __restrict__ out)
{
    extern __shared__ float sm[];
    __shared__ u64 sbar;
    __shared__ float wr1[8];
    __shared__ float wr2[8];
    __shared__ float s_half;

    const int bid = blockIdx.x;
    const int tid = threadIdx.x;
    const int lane = tid & 31;
    const int warp = tid >> 5;

    // ========== Phase 1: prep, A/C split (8 rows/block, half of W1) =========
    {
        float* W1s = sm;            // [d_local * 128 + k], d_local in 0..63
        float* xs  = sm + 8192;     // [r * 64 + d]
        const bool isA = (bid < 128);
        const int i0 = (isA ? bid : bid - 128) * 8;
        const int k = tid & 127;
        const int rh = tid >> 7;    // row half: rows i0+rh*4 .. +3

        // zero accumulators
        if (tid < 8) {
            if (isA) g_P[i0 + tid] = 0.f;
            else     g_R[i0 + tid] = 0.f;
        }
        if (bid == 0 && tid == 255) g_t[0] = 0.f;

        // coalesced copy: W1 half (2048 float4) + x rows (128 float4)
        {
            const float4* Wv = (const float4*)(W1 + (isA ? 0 : DIN * DHID));
            float4* Ws = (float4*)W1s;
#pragma unroll
            for (int e = 0; e < 8; e++)
                Ws[e * 256 + tid] = Wv[e * 256 + tid];
            const float4* xv = (const float4*)(x + (size_t)i0 * DIN);
            float4* xd = (float4*)xs;
            if (tid < 128) xd[tid] = xv[tid];
        }
        __syncthreads();

        float acc[4];
        const float init = isA ? b1[k] : 0.f;
#pragma unroll
        for (int q = 0; q < 4; q++) acc[q] = init;

        const float* wbase = W1s + k;
#pragma unroll
        for (int d4 = 0; d4 < DIN / 4; d4++) {
            float wv[4];
#pragma unroll
            for (int u = 0; u < 4; u++)
                wv[u] = wbase[(d4 * 4 + u) * DHID];
#pragma unroll
            for (int q = 0; q < 4; q++) {
                const float4 xvv = *(const float4*)&xs[(rh * 4 + q) * DIN + d4 * 4];
                acc[q] = fmaf(xvv.x, wv[0], acc[q]);
                acc[q] = fmaf(xvv.y, wv[1], acc[q]);
                acc[q] = fmaf(xvv.z, wv[2], acc[q]);
                acc[q] = fmaf(xvv.w, wv[3], acc[q]);
            }
        }
        float* dst = isA ? g_At : g_Ct;
        *(float4*)&dst[k * BDIM + i0 + rh * 4] =
            make_float4(acc[0], acc[1], acc[2], acc[3]);
    }

    grid_barrier(&g_cnt1, &sbar);

    // ========== Phase 2: sortstats (R13) on blocks 0..127 ===================
    if (bid < DHID) {
        float* sc   = sm;                // 8*132
        float* ssf  = sm + 1056;
        float* ssf2 = sm + 2112;
        const int k = bid;

        const float4 cv4 = *(const float4*)&g_Ct[k * BDIM + tid * 4];
        const float c[4] = {cv4.x, cv4.y, cv4.z, cv4.w};
        float v[4] = {c[0], c[1], c[2], c[3]};

        for (int size = 2; size <= 128; size <<= 1) {
            for (int stride = size >> 1; stride > 0; stride >>= 1) {
                float pv[4];
                if (stride >= 4) {
#pragma unroll
                    for (int r = 0; r < 4; r++)
                        pv[r] = __shfl_xor_sync(0xffffffffu, v[r], stride >> 2);
                } else {
#pragma unroll
                    for (int r = 0; r < 4; r++) pv[r] = v[r ^ stride];
                }
#pragma unroll
                for (int r = 0; r < 4; r++) {
                    const int le = lane * 4 + r;
                    const bool up = ((le & size) == 0);
                    const bool lower = ((le & stride) == 0);
                    const float mn = fminf(v[r], pv[r]);
                    const float mx = fmaxf(v[r], pv[r]);
                    v[r] = (up == lower) ? mn : mx;
                }
            }
        }

        float ls1[4], ls2[4];
        ls1[3] = v[3];               ls2[3] = v[3] * v[3];
        ls1[2] = ls1[3] + v[2];      ls2[2] = fmaf(v[2], v[2], ls2[3]);
        ls1[1] = ls1[2] + v[1];      ls2[1] = fmaf(v[1], v[1], ls2[2]);
        ls1[0] = ls1[1] + v[0];      ls2[0] = fmaf(v[0], v[0], ls2[1]);

        float w1 = ls1[0], w2 = ls2[0];
#pragma unroll
        for (int o = 1; o < 32; o <<= 1) {
            const float t1 = __shfl_down_sync(0xffffffffu, w1, o);
            const float t2 = __shfl_down_sync(0xffffffffu, w2, o);
            if (lane + o < 32) { w1 += t1; w2 += t2; }
        }
        const float base1 = w1 - ls1[0];
        const float base2 = w2 - ls2[0];

        const int cb = warp * 132;
#pragma unroll
        for (int r = 0; r < 4; r++) {
            const int le = lane * 4 + r;
            sc[cb + le]   = v[r];
            ssf[cb + le]  = ls1[r] + base1;
            ssf2[cb + le] = ls2[r] + base2;
        }
        if (lane == 0) {
            sc[cb + 128]   = __int_as_float(0x7f800000);
            ssf[cb + 128]  = 0.f;
            ssf2[cb + 128] = 0.f;
        }
        __syncthreads();

        const float4 av4 = *(const float4*)&g_At[k * BDIM + tid * 4];
        const float av[4] = {av4.x, av4.y, av4.z, av4.w};
        float S = 0.f, Q = 0.f;
#pragma unroll
        for (int r = 0; r < 4; r++) {
            const float a = av[r];
            const float th = -a;
            float ntot = 0.f, s1t = 0.f, s2t = 0.f;
#pragma unroll
            for (int m = 0; m < 8; m++) {
                const int base = m * 132;
                int lo = 0, hi = 128;
#pragma unroll
                for (int it = 0; it < 8; it++) {
                    const int mid = (lo + hi) >> 1;
                    if (sc[base + mid] > th) hi = mid; else lo = mid + 1;
                }
                ntot += (float)(128 - lo);
                s1t  += ssf[base + lo];
                s2t  += ssf2[base + lo];
            }
            S += fmaf(ntot, a, s1t);
            Q += fmaf(ntot * a, a, fmaf(2.f * a, s1t, s2t));
        }

#pragma unroll
        for (int o = 16; o > 0; o >>= 1) {
            S += __shfl_xor_sync(0xffffffffu, S, o);
            Q += __shfl_xor_sync(0xffffffffu, Q, o);
        }
        if (lane == 0) { wr1[warp] = S; wr2[warp] = Q; }
        __syncthreads();
        if (tid == 0) {
            float St = 0.f, Qt = 0.f;
#pragma unroll
            for (int w = 0; w < 8; w++) { St += wr1[w]; Qt += wr2[w]; }
            const float N = (float)BDIM * (float)BDIM;
            const float mean = St / N;
            const float var  = Qt / N - mean * mean;
            const float rs   = rsqrtf(var + BN_EPS);
            const float wk   = W2[k];
            const float sv   = gamma[k] * rs * wk;
            g_s[k] = sv;
            s_half = 0.5f * sv;
            atomicAdd(&g_t[0], (beta[k] - mean * rs * gamma[k]) * wk);
        }
        __syncthreads();

        const float sh = s_half;
#pragma unroll
        for (int r = 0; r < 4; r++) {
            atomicAdd(&g_P[tid * 4 + r], sh * av[r]);
            atomicAdd(&g_R[tid * 4 + r], sh * c[r]);
        }
    }

    grid_barrier(&g_cnt2, &sbar);

    // ========== Phase 3: pass2 (R2) =========================================
    {
        float* As  = sm;                       // [kk*64 + i]
        float* Cs  = sm + 4096;                // [kk*64 + j]
        u64*   s2h = (u64*)(sm + 8192);        // 128 u64
        float* Ps  = sm + 8448;
        float* Rs  = sm + 8512;

        const int i0 = (bid >> 4) * 64;
        const int j0 = (bid & 15) * 64;

        if (tid < DHID) {
            u64 p;
            asm("mov.b64 %0, {%1, %1};" : "=l"(p) : "f"(0.5f * g_s[tid]));
            s2h[tid] = p;
        }
        if (tid < 64) Ps[tid] = g_P[i0 + tid];
        else if (tid < 128) Rs[tid - 64] = g_R[j0 + tid - 64];

        const int ty = tid >> 4;
        const int tx = tid & 15;

        u64 acc2[4][2];
#pragma unroll
        for (int q = 0; q < 4; q++) { acc2[q][0] = 0ull; acc2[q][1] = 0ull; }
        const u64 MASK = 0x7FFFFFFF7FFFFFFFull;

        for (int kc = 0; kc < 2; kc++) {
            __syncthreads();
            for (int e = tid; e < 64 * 16; e += 256) {
                const int kk = e >> 4, vv = e & 15;
                const int kg = kc * 64 + kk;
                *(float4*)&As[kk * 64 + vv * 4] = *(const float4*)&g_At[kg * BDIM + i0 + vv * 4];
                *(float4*)&Cs[kk * 64 + vv * 4] = *(const float4*)&g_Ct[kg * BDIM + j0 + vv * 4];
            }
            __syncthreads();

#pragma unroll 8
            for (int kk = 0; kk < 64; kk++) {
                const float4 a4 = *(const float4*)&As[kk * 64 + ty * 4];
                const ulonglong2 cp = *(const ulonglong2*)&Cs[kk * 64 + tx * 4];
                const u64 sk = s2h[kc * 64 + kk];
                u64 av[4];
                asm("mov.b64 %0, {%1, %1};" : "=l"(av[0]) : "f"(a4.x));
                asm("mov.b64 %0, {%1, %1};" : "=l"(av[1]) : "f"(a4.y));
                asm("mov.b64 %0, {%1, %1};" : "=l"(av[2]) : "f"(a4.z));
                asm("mov.b64 %0, {%1, %1};" : "=l"(av[3]) : "f"(a4.w));
                const u64 cj[2] = {cp.x, cp.y};
#pragma unroll
                for (int q = 0; q < 4; q++) {
#pragma unroll
                    for (int r = 0; r < 2; r++) {
                        u64 vs;
                        asm("add.rn.f32x2 %0, %1, %2;" : "=l"(vs) : "l"(av[q]), "l"(cj[r]));
                        vs &= MASK;
                        asm("fma.rn.f32x2 %0, %1, %2, %3;"
                            : "=l"(acc2[q][r]) : "l"(vs), "l"(sk), "l"(acc2[q][r]));
                    }
                }
            }
        }

        const float t = g_t[0] + b2[0];
        const float r0 = Rs[tx * 4 + 0];
        const float r1 = Rs[tx * 4 + 1];
        const float r2 = Rs[tx * 4 + 2];
        const float r3 = Rs[tx * 4 + 3];
#pragma unroll
        for (int q = 0; q < 4; q++) {
            float v0, v1, v2, v3;
            asm("mov.b64 {%0, %1}, %2;" : "=f"(v0), "=f"(v1) : "l"(acc2[q][0]));
            asm("mov.b64 {%0, %1}, %2;" : "=f"(v2), "=f"(v3) : "l"(acc2[q][1]));
            const float base = t + Ps[ty * 4 + q];
            float4 o;
            o.x = v0 + base + r0;
            o.y = v1 + base + r1;
            o.z = v2 + base + r2;
            o.w = v3 + base + r3;
            *(float4*)&out[(size_t)(i0 + ty * 4 + q) * BDIM + j0 + tx * 4] = o;
        }
    }
}

// ---------------------------------------------------------------------------
extern "C" void kernel_launch(void* const* d_in, const int* in_sizes, int n_in,
                              void* d_out, int out_size)
{
    const float* x     = (const float*)d_in[0];
    const float* W1    = (const float*)d_in[1];
    const float* b1    = (const float*)d_in[2];
    const float* gamma = (const float*)d_in[3];
    const float* beta  = (const float*)d_in[4];
    const float* W2    = (const float*)d_in[5];
    const float* b2    = (const float*)d_in[6];
    float* out = (float*)d_out;

    cudaFuncSetAttribute(fused_kernel,
                         cudaFuncAttributeMaxDynamicSharedMemorySize, SMEM_BYTES);

    fused_kernel<<<NBLK, 256, SMEM_BYTES>>>(x, W1, b1, gamma, beta, W2, b2, out);
}